// round 15
// baseline (speedup 1.0000x reference)
#include <cuda_runtime.h>
#include <math.h>
#include <stdint.h>

// Net_43490838839931: batched RK4 of ds/dt = MLP([s,u]) with 2->4->1 LeakyReLU net.
// R9: attack the fma-pipe throughput wall (40 rt2-ops/el-step = 27.4us @2GHz).
// All add-type ops become immediate-multiplier FFMAs (SASS FFMA R,R,IMM,R: rt=1,
// 2x tput): a+b = fma(a,1.0,b); 2t+w = fma(t,2.0,w); sum/6+s = fma(sum,1/6,s).
// abs/sign moves off the fma pipe onto the idle ALU pipe as one LOP3-imm each:
//   +|g| = g & 0x7fffffff ;  -|g| = g | 0x80000000   (sign-specialized 16-way).
// fma-pipe: 20*rt2 + 20*rt1 = 60 cyc-units/el-step (was 80). alu: 32. issue: 56.
// Math identical to R7/R8: incremental RK4 stages on affine hinge values.

#define NSTEPS 100

// fma with compile-time immediate multiplier (targets SASS FFMA-imm rt=1 path)
__device__ __forceinline__ float fmaim1(float a, float b) {   // a*1.0 + b
    float d; asm("fma.rn.f32 %0, %1, 0f3F800000, %2;" : "=f"(d) : "f"(a), "f"(b));
    return d;
}
__device__ __forceinline__ float fmaim2(float a, float b) {   // a*2.0 + b
    float d; asm("fma.rn.f32 %0, %1, 0f40000000, %2;" : "=f"(d) : "f"(a), "f"(b));
    return d;
}
__device__ __forceinline__ float fmaim6(float a, float b) {   // a*(1/6) + b
    float d; asm("fma.rn.f32 %0, %1, 0f3E2AAAAB, %2;" : "=f"(d) : "f"(a), "f"(b));
    return d;
}

// signed abs on the ALU pipe: one LOP3 with immediate
template <bool NEG>
__device__ __forceinline__ float sabs(float g) {
    uint32_t r = __float_as_uint(g);
    r = NEG ? (r | 0x80000000u) : (r & 0x7fffffffu);
    return __uint_as_float(r);
}

struct Uni {
    float R0, R1, R2, R3;      // q_j * w1a_j
    float hR0, hR1, hR2, hR3;  // 0.5 * R_j
    float P, hP;               // sum p_j*w1a_j, half of it
};

struct El {                    // per-element state
    float Qt, D0, D1, D2, D3, s;
};

template <int SGN>
__device__ __forceinline__ float dynsum(float g0, float g1, float g2, float g3,
                                        float lin) {
    float A0 = sabs<(SGN & 1) != 0>(g0);
    float A1 = sabs<(SGN & 2) != 0>(g1);
    float A2 = sabs<(SGN & 4) != 0>(g2);
    float A3 = sabs<(SGN & 8) != 0>(g3);
    float t01 = fmaim1(A0, A1);
    float t23 = fmaim1(A2, A3);
    float v   = fmaim1(t01, t23);
    return fmaim1(v, lin);
}

template <int SGN>
__device__ __forceinline__ void step1(const Uni& U, El& e) {
    // stage 1 at s
    float g0 = fmaf(e.s, U.R0, e.D0);
    float g1 = fmaf(e.s, U.R1, e.D1);
    float g2 = fmaf(e.s, U.R2, e.D2);
    float g3 = fmaf(e.s, U.R3, e.D3);
    float lin1 = fmaf(U.P, e.s, e.Qt);
    float k1 = dynsum<SGN>(g0, g1, g2, g3, lin1);
    // stage 2 at s + 0.5*k1 (incremental)
    float h0 = fmaf(k1, U.hR0, g0);
    float h1 = fmaf(k1, U.hR1, g1);
    float h2 = fmaf(k1, U.hR2, g2);
    float h3 = fmaf(k1, U.hR3, g3);
    float lin2 = fmaf(k1, U.hP, lin1);
    float k2 = dynsum<SGN>(h0, h1, h2, h3, lin2);
    // stage 3 at s + 0.5*k2
    float m0 = fmaf(k2, U.hR0, g0);
    float m1 = fmaf(k2, U.hR1, g1);
    float m2 = fmaf(k2, U.hR2, g2);
    float m3 = fmaf(k2, U.hR3, g3);
    float lin3 = fmaf(k2, U.hP, lin1);
    float k3 = dynsum<SGN>(m0, m1, m2, m3, lin3);
    // stage 4 at s + k3
    float n0 = fmaf(k3, U.R0, g0);
    float n1 = fmaf(k3, U.R1, g1);
    float n2 = fmaf(k3, U.R2, g2);
    float n3 = fmaf(k3, U.R3, g3);
    float lin4 = fmaf(k3, U.P, lin1);
    float k4 = dynsum<SGN>(n0, n1, n2, n3, lin4);
    // combine: s' = s + (k1 + 2k2 + 2k3 + k4)/6  — all imm-FFMAs
    float t = fmaim1(k2, k3);
    float w = fmaim1(k1, k4);
    float sum = fmaim2(t, w);
    e.s = fmaim6(sum, e.s);
}

template <int SGN>
__device__ __forceinline__ void run_loop(const Uni& U, El (&E)[2], float2 xv,
                                         float4* o0, float4* o1) {
    float4 w0, w1;
    // Group 0: t=0 is the initial state, then 3 steps.
    w0.x = xv.x; w1.x = xv.y;
    step1<SGN>(U, E[0]); step1<SGN>(U, E[1]);
    w0.y = E[0].s; w1.y = E[1].s;
    step1<SGN>(U, E[0]); step1<SGN>(U, E[1]);
    w0.z = E[0].s; w1.z = E[1].s;
    step1<SGN>(U, E[0]); step1<SGN>(U, E[1]);
    w0.w = E[0].s; w1.w = E[1].s;
    o0[0] = w0; o1[0] = w1;

    // Remaining 24 groups of 4 steps (96 steps -> 99 total).
    #pragma unroll 1
    for (int g = 1; g < NSTEPS / 4; ++g) {
        step1<SGN>(U, E[0]); step1<SGN>(U, E[1]);
        w0.x = E[0].s; w1.x = E[1].s;
        step1<SGN>(U, E[0]); step1<SGN>(U, E[1]);
        w0.y = E[0].s; w1.y = E[1].s;
        step1<SGN>(U, E[0]); step1<SGN>(U, E[1]);
        w0.z = E[0].s; w1.z = E[1].s;
        step1<SGN>(U, E[0]); step1<SGN>(U, E[1]);
        w0.w = E[0].s; w1.w = E[1].s;
        o0[g] = w0; o1[g] = w1;
    }
}

__global__ __launch_bounds__(32) void rk4_kernel(
    const float* __restrict__ x, const float* __restrict__ u,
    const float* __restrict__ W1, const float* __restrict__ b1,
    const float* __restrict__ W2, const float* __restrict__ b2,
    float* __restrict__ out, int B)
{
    int i = blockIdx.x * blockDim.x + threadIdx.x;
    int b0 = 2 * i;
    if (b0 >= B) return;

    float2 xv = reinterpret_cast<const float2*>(x)[i];
    float2 uv = reinterpret_cast<const float2*>(u)[i];

    // W1 [2,4] row-major: row 0 multiplies s, row 1 multiplies u.
    float a0 = W1[0], a1 = W1[1], a2 = W1[2], a3 = W1[3];
    float u0 = W1[4], u1 = W1[5], u2 = W1[6], u3 = W1[7];
    float v0 = W2[0], v1 = W2[1], v2 = W2[2], v3 = W2[3];

    float p0 = 0.505f * v0, p1 = 0.505f * v1, p2 = 0.505f * v2, p3 = 0.505f * v3;
    float q0 = 0.495f * v0, q1 = 0.495f * v1, q2 = 0.495f * v2, q3 = 0.495f * v3;
    float bb = b2[0];

    Uni U;
    U.R0 = q0 * a0; U.R1 = q1 * a1; U.R2 = q2 * a2; U.R3 = q3 * a3;
    U.hR0 = 0.5f * U.R0; U.hR1 = 0.5f * U.R1;
    U.hR2 = 0.5f * U.R2; U.hR3 = 0.5f * U.R3;
    U.P = fmaf(p0, a0, fmaf(p1, a1, fmaf(p2, a2, p3 * a3)));
    U.hP = 0.5f * U.P;

    const float us[2] = {uv.x, uv.y};
    const float xs[2] = {xv.x, xv.y};
    El E[2];
    #pragma unroll
    for (int e = 0; e < 2; ++e) {
        float c0 = fmaf(us[e], u0, b1[0]);
        float c1 = fmaf(us[e], u1, b1[1]);
        float c2 = fmaf(us[e], u2, b1[2]);
        float c3 = fmaf(us[e], u3, b1[3]);
        E[e].Qt = bb + fmaf(p0, c0, fmaf(p1, c1, fmaf(p2, c2, p3 * c3)));
        E[e].D0 = q0 * c0; E[e].D1 = q1 * c1;
        E[e].D2 = q2 * c2; E[e].D3 = q3 * c3;
        E[e].s = xs[e];
    }

    float4* o0 = reinterpret_cast<float4*>(out + (size_t)b0 * NSTEPS);
    float4* o1 = reinterpret_cast<float4*>(out + (size_t)(b0 + 1) * NSTEPS);

    // 4-bit sign code of W2 (uniform across all threads -> no divergence).
    int code = (v0 < 0.0f ? 1 : 0) | (v1 < 0.0f ? 2 : 0) |
               (v2 < 0.0f ? 4 : 0) | (v3 < 0.0f ? 8 : 0);

    switch (code) {
        case 0:  run_loop<0 >(U, E, xv, o0, o1); break;
        case 1:  run_loop<1 >(U, E, xv, o0, o1); break;
        case 2:  run_loop<2 >(U, E, xv, o0, o1); break;
        case 3:  run_loop<3 >(U, E, xv, o0, o1); break;
        case 4:  run_loop<4 >(U, E, xv, o0, o1); break;
        case 5:  run_loop<5 >(U, E, xv, o0, o1); break;
        case 6:  run_loop<6 >(U, E, xv, o0, o1); break;
        case 7:  run_loop<7 >(U, E, xv, o0, o1); break;
        case 8:  run_loop<8 >(U, E, xv, o0, o1); break;
        case 9:  run_loop<9 >(U, E, xv, o0, o1); break;
        case 10: run_loop<10>(U, E, xv, o0, o1); break;
        case 11: run_loop<11>(U, E, xv, o0, o1); break;
        case 12: run_loop<12>(U, E, xv, o0, o1); break;
        case 13: run_loop<13>(U, E, xv, o0, o1); break;
        case 14: run_loop<14>(U, E, xv, o0, o1); break;
        case 15: run_loop<15>(U, E, xv, o0, o1); break;
    }
}

extern "C" void kernel_launch(void* const* d_in, const int* in_sizes, int n_in,
                              void* d_out, int out_size)
{
    const float* x  = (const float*)d_in[0];
    const float* u  = (const float*)d_in[1];
    const float* W1 = (const float*)d_in[2];
    const float* b1 = (const float*)d_in[3];
    const float* W2 = (const float*)d_in[4];
    const float* b2 = (const float*)d_in[5];
    float* out = (float*)d_out;
    int B = in_sizes[0];

    int nthreads = B / 2;                // 2 elements per thread (2 scalar chains)
    int threads = 32;                    // 2048 blocks
    int blocks = (nthreads + threads - 1) / threads;
    rk4_kernel<<<blocks, threads>>>(x, u, W1, b1, W2, b2, out, B);
}

// round 16
// speedup vs baseline: 1.0590x; 1.0590x over previous
#include <cuda_runtime.h>
#include <math.h>
#include <stdint.h>

// Net_43490838839931: batched RK4 of ds/dt = MLP([s,u]) with 2->4->1 LeakyReLU net.
// R10: beat the fma-pipe rt2 wall via FFMA-imm (rt_SMSP=1) adds that ptxas CANNOT
// canonicalize to FADD: hinge channels pre-scaled by powers of 2 (folded into
// constants, exact), so the dynsum tree is all multiplier-2.0 FFMAs:
//   a0@1/8, a1@1/4, a2@1/4, a3@1/2:
//   t01=fma(a0,2,a1)=(a0+a1)/4 ; t23=fma(a2,2,a3)=(a2+a3)/2
//   v=fma(t01,2,t23)=S/2 ; k=fma(v,2,lin)=S+lin
// combine: sum=fma(t,2,w), s'=fma(sum,1/6,s) also imm-FFMA.
// signed-abs on ALU pipe (LOP3-imm), sign-specialized 16-way.
// fma-pipe: 20*rt2 + 2*rt2 + 18*rt1 = 62 cyc/el-step (was 80).

#define NSTEPS 100

// a*2.0f + b  -> SASS FFMA R,R,IMM,R (rt=1); cannot canonicalize to FADD.
__device__ __forceinline__ float fma2i(float a, float b) {
    float d; asm("fma.rn.f32 %0, %1, 0f40000000, %2;" : "=f"(d) : "f"(a), "f"(b));
    return d;
}
// a*(1/6) + b
__device__ __forceinline__ float fma6i(float a, float b) {
    float d; asm("fma.rn.f32 %0, %1, 0f3E2AAAAB, %2;" : "=f"(d) : "f"(a), "f"(b));
    return d;
}

// signed abs on the ALU pipe: one LOP3 with immediate
template <bool NEG>
__device__ __forceinline__ float sabs(float g) {
    uint32_t r = __float_as_uint(g);
    r = NEG ? (r | 0x80000000u) : (r & 0x7fffffffu);
    return __uint_as_float(r);
}

struct Uni {
    float R0, R1, R2, R3;      // q_j*w1a_j, pre-scaled by SC_j
    float hR0, hR1, hR2, hR3;  // 0.5 * scaled R_j
    float P, hP;               // linear part (unscaled)
};

struct El {                    // per-element state (D_j pre-scaled by SC_j)
    float Qt, D0, D1, D2, D3, s;
};

// channel scales: a0@1/8, a1@1/4, a2@1/4, a3@1/2
#define SC0 0.125f
#define SC1 0.25f
#define SC2 0.25f
#define SC3 0.5f

template <int SGN>
__device__ __forceinline__ float dynsum(float g0, float g1, float g2, float g3,
                                        float lin) {
    float A0 = sabs<(SGN & 1) != 0>(g0);   // = sgn0*|a0|/8
    float A1 = sabs<(SGN & 2) != 0>(g1);   // = sgn1*|a1|/4
    float A2 = sabs<(SGN & 4) != 0>(g2);   // = sgn2*|a2|/4
    float A3 = sabs<(SGN & 8) != 0>(g3);   // = sgn3*|a3|/2
    float t01 = fma2i(A0, A1);             // (a0+a1)/4
    float t23 = fma2i(A2, A3);             // (a2+a3)/2
    float v   = fma2i(t01, t23);           // (a0+a1+a2+a3)/2
    return fma2i(v, lin);                  // sum + lin  (full scale)
}

template <int SGN>
__device__ __forceinline__ void step1(const Uni& U, El& e) {
    // stage 1 at s (hinges at per-channel scale; k full scale)
    float g0 = fmaf(e.s, U.R0, e.D0);
    float g1 = fmaf(e.s, U.R1, e.D1);
    float g2 = fmaf(e.s, U.R2, e.D2);
    float g3 = fmaf(e.s, U.R3, e.D3);
    float lin1 = fmaf(U.P, e.s, e.Qt);
    float k1 = dynsum<SGN>(g0, g1, g2, g3, lin1);
    // stage 2 at s + 0.5*k1 (incremental, scale preserved per channel)
    float h0 = fmaf(k1, U.hR0, g0);
    float h1 = fmaf(k1, U.hR1, g1);
    float h2 = fmaf(k1, U.hR2, g2);
    float h3 = fmaf(k1, U.hR3, g3);
    float lin2 = fmaf(k1, U.hP, lin1);
    float k2 = dynsum<SGN>(h0, h1, h2, h3, lin2);
    // stage 3 at s + 0.5*k2
    float m0 = fmaf(k2, U.hR0, g0);
    float m1 = fmaf(k2, U.hR1, g1);
    float m2 = fmaf(k2, U.hR2, g2);
    float m3 = fmaf(k2, U.hR3, g3);
    float lin3 = fmaf(k2, U.hP, lin1);
    float k3 = dynsum<SGN>(m0, m1, m2, m3, lin3);
    // stage 4 at s + k3
    float n0 = fmaf(k3, U.R0, g0);
    float n1 = fmaf(k3, U.R1, g1);
    float n2 = fmaf(k3, U.R2, g2);
    float n3 = fmaf(k3, U.R3, g3);
    float lin4 = fmaf(k3, U.P, lin1);
    float k4 = dynsum<SGN>(n0, n1, n2, n3, lin4);
    // combine: s' = s + (k1 + 2k2 + 2k3 + k4)/6
    float t = k2 + k3;
    float w = k1 + k4;
    float sum = fma2i(t, w);     // 2(k2+k3) + (k1+k4)
    e.s = fma6i(sum, e.s);       // /6 + s
}

template <int SGN>
__device__ __forceinline__ void run_loop(const Uni& U, El (&E)[2], float2 xv,
                                         float4* o0, float4* o1) {
    float4 w0, w1;
    // Group 0: t=0 is the initial state, then 3 steps.
    w0.x = xv.x; w1.x = xv.y;
    step1<SGN>(U, E[0]); step1<SGN>(U, E[1]);
    w0.y = E[0].s; w1.y = E[1].s;
    step1<SGN>(U, E[0]); step1<SGN>(U, E[1]);
    w0.z = E[0].s; w1.z = E[1].s;
    step1<SGN>(U, E[0]); step1<SGN>(U, E[1]);
    w0.w = E[0].s; w1.w = E[1].s;
    o0[0] = w0; o1[0] = w1;

    // Remaining 24 groups of 4 steps (96 steps -> 99 total).
    #pragma unroll 1
    for (int g = 1; g < NSTEPS / 4; ++g) {
        step1<SGN>(U, E[0]); step1<SGN>(U, E[1]);
        w0.x = E[0].s; w1.x = E[1].s;
        step1<SGN>(U, E[0]); step1<SGN>(U, E[1]);
        w0.y = E[0].s; w1.y = E[1].s;
        step1<SGN>(U, E[0]); step1<SGN>(U, E[1]);
        w0.z = E[0].s; w1.z = E[1].s;
        step1<SGN>(U, E[0]); step1<SGN>(U, E[1]);
        w0.w = E[0].s; w1.w = E[1].s;
        o0[g] = w0; o1[g] = w1;
    }
}

__global__ __launch_bounds__(32) void rk4_kernel(
    const float* __restrict__ x, const float* __restrict__ u,
    const float* __restrict__ W1, const float* __restrict__ b1,
    const float* __restrict__ W2, const float* __restrict__ b2,
    float* __restrict__ out, int B)
{
    int i = blockIdx.x * blockDim.x + threadIdx.x;
    int b0 = 2 * i;
    if (b0 >= B) return;

    float2 xv = reinterpret_cast<const float2*>(x)[i];
    float2 uv = reinterpret_cast<const float2*>(u)[i];

    // W1 [2,4] row-major: row 0 multiplies s, row 1 multiplies u.
    float a0 = W1[0], a1 = W1[1], a2 = W1[2], a3 = W1[3];
    float u0 = W1[4], u1 = W1[5], u2 = W1[6], u3 = W1[7];
    float v0 = W2[0], v1 = W2[1], v2 = W2[2], v3 = W2[3];

    float p0 = 0.505f * v0, p1 = 0.505f * v1, p2 = 0.505f * v2, p3 = 0.505f * v3;
    float q0 = 0.495f * v0, q1 = 0.495f * v1, q2 = 0.495f * v2, q3 = 0.495f * v3;
    float bb = b2[0];

    float R0 = q0 * a0, R1 = q1 * a1, R2 = q2 * a2, R3 = q3 * a3;

    Uni U;
    U.R0 = R0 * SC0; U.R1 = R1 * SC1; U.R2 = R2 * SC2; U.R3 = R3 * SC3;
    U.hR0 = 0.5f * U.R0; U.hR1 = 0.5f * U.R1;
    U.hR2 = 0.5f * U.R2; U.hR3 = 0.5f * U.R3;
    U.P = fmaf(p0, a0, fmaf(p1, a1, fmaf(p2, a2, p3 * a3)));
    U.hP = 0.5f * U.P;

    const float us[2] = {uv.x, uv.y};
    const float xs[2] = {xv.x, xv.y};
    El E[2];
    #pragma unroll
    for (int e = 0; e < 2; ++e) {
        float c0 = fmaf(us[e], u0, b1[0]);
        float c1 = fmaf(us[e], u1, b1[1]);
        float c2 = fmaf(us[e], u2, b1[2]);
        float c3 = fmaf(us[e], u3, b1[3]);
        E[e].Qt = bb + fmaf(p0, c0, fmaf(p1, c1, fmaf(p2, c2, p3 * c3)));
        E[e].D0 = (q0 * c0) * SC0; E[e].D1 = (q1 * c1) * SC1;
        E[e].D2 = (q2 * c2) * SC2; E[e].D3 = (q3 * c3) * SC3;
        E[e].s = xs[e];
    }

    float4* o0 = reinterpret_cast<float4*>(out + (size_t)b0 * NSTEPS);
    float4* o1 = reinterpret_cast<float4*>(out + (size_t)(b0 + 1) * NSTEPS);

    // 4-bit sign code of W2 (uniform across all threads -> no divergence).
    int code = (v0 < 0.0f ? 1 : 0) | (v1 < 0.0f ? 2 : 0) |
               (v2 < 0.0f ? 4 : 0) | (v3 < 0.0f ? 8 : 0);

    switch (code) {
        case 0:  run_loop<0 >(U, E, xv, o0, o1); break;
        case 1:  run_loop<1 >(U, E, xv, o0, o1); break;
        case 2:  run_loop<2 >(U, E, xv, o0, o1); break;
        case 3:  run_loop<3 >(U, E, xv, o0, o1); break;
        case 4:  run_loop<4 >(U, E, xv, o0, o1); break;
        case 5:  run_loop<5 >(U, E, xv, o0, o1); break;
        case 6:  run_loop<6 >(U, E, xv, o0, o1); break;
        case 7:  run_loop<7 >(U, E, xv, o0, o1); break;
        case 8:  run_loop<8 >(U, E, xv, o0, o1); break;
        case 9:  run_loop<9 >(U, E, xv, o0, o1); break;
        case 10: run_loop<10>(U, E, xv, o0, o1); break;
        case 11: run_loop<11>(U, E, xv, o0, o1); break;
        case 12: run_loop<12>(U, E, xv, o0, o1); break;
        case 13: run_loop<13>(U, E, xv, o0, o1); break;
        case 14: run_loop<14>(U, E, xv, o0, o1); break;
        case 15: run_loop<15>(U, E, xv, o0, o1); break;
    }
}

extern "C" void kernel_launch(void* const* d_in, const int* in_sizes, int n_in,
                              void* d_out, int out_size)
{
    const float* x  = (const float*)d_in[0];
    const float* u  = (const float*)d_in[1];
    const float* W1 = (const float*)d_in[2];
    const float* b1 = (const float*)d_in[3];
    const float* W2 = (const float*)d_in[4];
    const float* b2 = (const float*)d_in[5];
    float* out = (float*)d_out;
    int B = in_sizes[0];

    int nthreads = B / 2;                // 2 elements per thread (2 scalar chains)
    int threads = 32;                    // 2048 blocks
    int blocks = (nthreads + threads - 1) / threads;
    rk4_kernel<<<blocks, threads>>>(x, u, W1, b1, W2, b2, out, B);
}